// round 15
// baseline (speedup 1.0000x reference)
#include <cuda_runtime.h>
#include <cuda_fp16.h>
#include <math.h>
#include <stdint.h>

#define Hdim 4544
#define Sdim 1024
#define NHh  71
#define HDd  64
#define FFNd 18176
#define QKVN 4672              // NH*HD + 2*HD
#define KOFF 4544
#define VOFF 4608
#define INV_NORM 0.125f
#define EPSf 1e-5f

// ---------------- scratch (__device__ globals; allocation-free rule) -------
__device__ __align__(16) float  g_qkv[Sdim * QKVN];
__device__ __align__(16) float  g_attn[Sdim * Hdim];
__device__ __align__(16) __half g_ln_h[Sdim * Hdim];
__device__ __align__(16) __half g_ctx_h[Sdim * Hdim];
__device__ __align__(16) __half g_fc_h[(size_t)Sdim * FFNd];
__device__ __align__(16) __half g_w_qkv_h[(size_t)Hdim * QKVN];
__device__ __align__(16) __half g_w_dense_h[(size_t)Hdim * Hdim];
__device__ __align__(16) __half g_w_fc_h[(size_t)Hdim * FFNd];
__device__ __align__(16) __half g_w_proj_h[(size_t)FFNd * Hdim];

// ---------------------------------------------------------------------------
// PTX helpers (compute_103-safe)
// ---------------------------------------------------------------------------
__device__ __forceinline__ uint32_t smem_u32(const void* p) {
    uint32_t a;
    asm("{ .reg .u64 t; cvta.to.shared.u64 t, %1; cvt.u32.u64 %0, t; }" : "=r"(a) : "l"(p));
    return a;
}

#define CP_ASYNC16(dst, src) \
    asm volatile("cp.async.cg.shared.global [%0], [%1], 16;" :: "r"(dst), "l"(src) : "memory")
#define CP_ASYNC16_Z(dst, src, sz) \
    asm volatile("cp.async.cg.shared.global [%0], [%1], 16, %2;" :: "r"(dst), "l"(src), "r"(sz) : "memory")
#define CP_COMMIT() asm volatile("cp.async.commit_group;" ::: "memory")
#define CP_WAIT1()  asm volatile("cp.async.wait_group 1;" ::: "memory")

#define LDSM_X4(r0, r1, r2, r3, addr)                                        \
    asm volatile("ldmatrix.sync.aligned.m8n8.x4.shared.b16 {%0,%1,%2,%3}, [%4];" \
        : "=r"(r0), "=r"(r1), "=r"(r2), "=r"(r3) : "r"(addr))
#define LDSM_X4T(r0, r1, r2, r3, addr)                                       \
    asm volatile("ldmatrix.sync.aligned.m8n8.x4.trans.shared.b16 {%0,%1,%2,%3}, [%4];" \
        : "=r"(r0), "=r"(r1), "=r"(r2), "=r"(r3) : "r"(addr))

__device__ __forceinline__ void mma_f16(float* c, const uint32_t* a,
                                        uint32_t b0, uint32_t b1) {
    asm volatile(
        "mma.sync.aligned.m16n8k16.row.col.f32.f16.f16.f32 "
        "{%0,%1,%2,%3}, {%4,%5,%6,%7}, {%8,%9}, {%0,%1,%2,%3};"
        : "+f"(c[0]), "+f"(c[1]), "+f"(c[2]), "+f"(c[3])
        : "r"(a[0]), "r"(a[1]), "r"(a[2]), "r"(a[3]), "r"(b0), "r"(b1));
}

// ---------------------------------------------------------------------------
// f16 mma GEMM:  C[1024, N] = A[1024, K](f16) @ B[K, N](f16)   row-major both
// CTA 128x128, BK=64, 8 warps (4m x 2n), warp tile 32x64, 3-stage cp.async.
// Mainloop: all A fragments for the BK block are loaded upfront, then B
// fragments stream one quad at a time, each immediately feeding its 4 MMAs —
// keeps the tensor pipe fed during LDSM bursts.
// EPI: 0 none (fp32 out), 1 exact GELU (f16 out), 2 += r1 + r2 (fp32 out)
// ---------------------------------------------------------------------------
#define BM 128
#define BN 128
#define BK 64
#define A_STRIDE 144           // bytes per m-row: 64 f16 (128B) + 16 pad
#define B_STRIDE 272           // bytes per k-row: 128 f16 (256B) + 16 pad
#define A_SZ (BM * A_STRIDE)
#define B_SZ (BK * B_STRIDE)
#define STAGE_SZ (A_SZ + B_SZ)
#define NSTAGE 3
#define GEMM_SMEM (NSTAGE * STAGE_SZ)

template <int EPI>
__global__ void __launch_bounds__(256, 2) hgemm(
    const __half* __restrict__ A, const __half* __restrict__ B,
    void* __restrict__ Cout, int N, int K,
    const float* __restrict__ r1, const float* __restrict__ r2) {
    extern __shared__ char smem[];
    uint32_t sb = smem_u32(smem);
    int tid = threadIdx.x;
    int m0 = blockIdx.x * BM, n0 = blockIdx.y * BN;
    int wid = tid >> 5, lane = tid & 31;
    int wm = (wid & 3) * 32, wn = (wid >> 2) * 64;
    int g = lane >> 2, q = lane & 3;

    float acc[2][8][4];
#pragma unroll
    for (int f = 0; f < 2; f++)
#pragma unroll
        for (int j = 0; j < 8; j++)
#pragma unroll
            for (int e = 0; e < 4; e++) acc[f][j][e] = 0.f;

    int nk = K / BK;

    auto issue = [&](int it) {
        uint32_t base = sb + (uint32_t)(it % NSTAGE) * STAGE_SZ;
        int k0 = it * BK;
#pragma unroll
        for (int u = 0; u < 4; u++) {
            int ch = tid + u * 256;
            int r = ch >> 3, c = ch & 7;
            CP_ASYNC16(base + r * A_STRIDE + c * 16,
                       A + (size_t)(m0 + r) * K + k0 + c * 8);
        }
        uint32_t bb = base + A_SZ;
#pragma unroll
        for (int u = 0; u < 4; u++) {
            int ch = tid + u * 256;
            int r = ch >> 4, c = ch & 15;
            int col = n0 + c * 8;
            uint32_t sz = (col < N) ? 16u : 0u;
            const __half* src = B + (size_t)(k0 + r) * N + (col < N ? col : 0);
            CP_ASYNC16_Z(bb + r * B_STRIDE + c * 16, src, sz);
        }
    };

    issue(0); CP_COMMIT();
    issue(1); CP_COMMIT();

    for (int i = 0; i < nk; i++) {
        CP_WAIT1();
        __syncthreads();
        if (i + 2 < nk) issue(i + 2);
        CP_COMMIT();

        uint32_t As = sb + (uint32_t)(i % NSTAGE) * STAGE_SZ;
        uint32_t Bs = As + A_SZ;

        // 1) all A fragments for the BK=64 block (reused by 8 N-frags each)
        uint32_t a[4][2][4];
#pragma unroll
        for (int ks = 0; ks < 4; ks++)
#pragma unroll
            for (int f = 0; f < 2; f++) {
                uint32_t addr = As + (wm + f * 16 + (lane & 15)) * A_STRIDE +
                                ((lane >> 4) << 4) + ks * 32;
                LDSM_X4(a[ks][f][0], a[ks][f][1], a[ks][f][2], a[ks][f][3], addr);
            }

        // 2) stream B: one LDSM quad -> 4 MMAs, interleaved
#pragma unroll
        for (int ks = 0; ks < 4; ks++) {
#pragma unroll
            for (int u = 0; u < 4; u++) {
                uint32_t b0, b1, b2, b3;
                uint32_t addr = Bs + (ks * 16 + (lane & 15)) * B_STRIDE +
                                (wn + u * 16 + ((lane >> 4) << 3)) * 2;
                LDSM_X4T(b0, b1, b2, b3, addr);
                mma_f16(acc[0][2 * u],     a[ks][0], b0, b1);
                mma_f16(acc[1][2 * u],     a[ks][1], b0, b1);
                mma_f16(acc[0][2 * u + 1], a[ks][0], b2, b3);
                mma_f16(acc[1][2 * u + 1], a[ks][1], b2, b3);
            }
        }
    }

#pragma unroll
    for (int f = 0; f < 2; f++) {
        int row = m0 + wm + f * 16 + g;
#pragma unroll
        for (int j = 0; j < 8; j++) {
            int col = n0 + wn + 8 * j + 2 * q;
            if (col >= N) continue;
            float v[4] = {acc[f][j][0], acc[f][j][1], acc[f][j][2], acc[f][j][3]};
            if (EPI == 1) {
#pragma unroll
                for (int e = 0; e < 4; e++)
                    v[e] = 0.5f * v[e] * (1.0f + erff(v[e] * 0.70710678118654752f));
                __half* C = (__half*)Cout;
                *(__half2*)(C + (size_t)row * N + col) = __floats2half2_rn(v[0], v[1]);
                *(__half2*)(C + (size_t)(row + 8) * N + col) = __floats2half2_rn(v[2], v[3]);
            } else {
                float* C = (float*)Cout;
                if (EPI == 2) {
                    size_t i0 = (size_t)row * N + col;
                    size_t i1 = (size_t)(row + 8) * N + col;
                    float2 a0 = *(const float2*)(r1 + i0);
                    float2 b0v = *(const float2*)(r2 + i0);
                    float2 a1 = *(const float2*)(r1 + i1);
                    float2 b1v = *(const float2*)(r2 + i1);
                    v[0] += a0.x + b0v.x; v[1] += a0.y + b0v.y;
                    v[2] += a1.x + b1v.x; v[3] += a1.y + b1v.y;
                }
                *(float2*)(C + (size_t)row * N + col)       = make_float2(v[0], v[1]);
                *(float2*)(C + (size_t)(row + 8) * N + col) = make_float2(v[2], v[3]);
            }
        }
    }
}

// ---------------------------------------------------------------------------
// fp32 -> f16 convert
// ---------------------------------------------------------------------------
__global__ void f2h_kernel(const float* __restrict__ in, __half* __restrict__ out,
                           size_t n) {
    size_t i = ((size_t)blockIdx.x * blockDim.x + threadIdx.x) * 4;
    size_t stride = (size_t)gridDim.x * blockDim.x * 4;
    for (; i < n; i += stride) {
        float4 v = *(const float4*)(in + i);
        __half2 h0 = __floats2half2_rn(v.x, v.y);
        __half2 h1 = __floats2half2_rn(v.z, v.w);
        uint2 pk;
        pk.x = *(uint32_t*)&h0;
        pk.y = *(uint32_t*)&h1;
        *(uint2*)(out + i) = pk;
    }
}

// ---------------------------------------------------------------------------
// LayerNorm -> f16 out
// ---------------------------------------------------------------------------
__global__ void ln_kernel(const float* __restrict__ x,
                          const float* __restrict__ w,
                          const float* __restrict__ b,
                          __half* __restrict__ out) {
    int row = blockIdx.x;
    const float4* xr = (const float4*)(x + (size_t)row * Hdim);
    float s = 0.f, ss = 0.f;
    for (int i = threadIdx.x; i < Hdim / 4; i += blockDim.x) {
        float4 v = xr[i];
        s  += v.x + v.y + v.z + v.w;
        ss += v.x * v.x + v.y * v.y + v.z * v.z + v.w * v.w;
    }
    __shared__ float rs[256], rq[256];
    rs[threadIdx.x] = s; rq[threadIdx.x] = ss;
    __syncthreads();
    for (int st = 128; st > 0; st >>= 1) {
        if (threadIdx.x < st) {
            rs[threadIdx.x] += rs[threadIdx.x + st];
            rq[threadIdx.x] += rq[threadIdx.x + st];
        }
        __syncthreads();
    }
    float mean = rs[0] / (float)Hdim;
    float var  = rq[0] / (float)Hdim - mean * mean;
    float inv  = rsqrtf(var + EPSf);
    const float4* wr = (const float4*)w;
    const float4* br = (const float4*)b;
    __half* outr = out + (size_t)row * Hdim;
    for (int i = threadIdx.x; i < Hdim / 4; i += blockDim.x) {
        float4 v = xr[i], wv = wr[i], bv = br[i];
        float o0 = (v.x - mean) * inv * wv.x + bv.x;
        float o1 = (v.y - mean) * inv * wv.y + bv.y;
        float o2 = (v.z - mean) * inv * wv.z + bv.z;
        float o3 = (v.w - mean) * inv * wv.w + bv.w;
        __half2 h0 = __floats2half2_rn(o0, o1);
        __half2 h1 = __floats2half2_rn(o2, o3);
        uint2 pk;
        pk.x = *(uint32_t*)&h0;
        pk.y = *(uint32_t*)&h1;
        *(uint2*)(outr + i * 4) = pk;
    }
}

// ---------------------------------------------------------------------------
// Flash-style causal attention, 32 queries/block (4 per warp).
// Causal mask computed arithmetically.
// ---------------------------------------------------------------------------
#define QB 32
__global__ void __launch_bounds__(256) attn_kernel(
    const float* __restrict__ qkv,
    const float* __restrict__ alibi,
    __half* __restrict__ ctx) {
    __shared__ float Qs[QB][65];
    __shared__ float Ks[32][65];
    __shared__ float Vs[32][65];

    int h  = blockIdx.x;
    int q0 = blockIdx.y * QB;
    int t    = threadIdx.x;
    int w    = t >> 5;
    int lane = t & 31;
    int qrow = w * 4;

    for (int i = t; i < QB * 64; i += 256) {
        int r = i >> 6, d = i & 63;
        Qs[r][d] = qkv[(size_t)(q0 + r) * QKVN + h * HDd + d];
    }
    __syncthreads();

    float m[4], l[4], c0[4], c1[4], p[4];
#pragma unroll
    for (int u = 0; u < 4; u++) { m[u] = -INFINITY; l[u] = 0.f; c0[u] = 0.f; c1[u] = 0.f; }

    int kend = q0 + QB - 1;

    for (int kc = 0; kc <= kend; kc += 32) {
        for (int i = t; i < 2048; i += 256) {
            int j = i >> 6, d = i & 63;
            size_t rb = (size_t)(kc + j) * QKVN;
            Ks[j][d] = qkv[rb + KOFF + d];
            Vs[j][d] = qkv[rb + VOFF + d];
        }
        __syncthreads();

        int kg = kc + lane;
        float s[4] = {0.f, 0.f, 0.f, 0.f};
#pragma unroll
        for (int d = 0; d < 64; d++) {
            float kv = Ks[lane][d];
            s[0] += Qs[qrow + 0][d] * kv;
            s[1] += Qs[qrow + 1][d] * kv;
            s[2] += Qs[qrow + 2][d] * kv;
            s[3] += Qs[qrow + 3][d] * kv;
        }
        float al = alibi[h * Sdim + kg];
#pragma unroll
        for (int u = 0; u < 4; u++) {
            int qg = q0 + qrow + u;
            float msk = (kg <= qg) ? 0.0f : -1000000000.0f;
            float su = (s[u] + al) * INV_NORM + msk;
            float cm = su;
#pragma unroll
            for (int o = 16; o; o >>= 1)
                cm = fmaxf(cm, __shfl_xor_sync(0xffffffffu, cm, o));
            float mnew = fmaxf(m[u], cm);
            float corr = __expf(m[u] - mnew);
            p[u] = __expf(su - mnew);
            float ps = p[u];
#pragma unroll
            for (int o = 16; o; o >>= 1)
                ps += __shfl_xor_sync(0xffffffffu, ps, o);
            l[u] = l[u] * corr + ps;
            c0[u] *= corr; c1[u] *= corr;
            m[u] = mnew;
        }
#pragma unroll
        for (int j = 0; j < 32; j++) {
            float v0 = Vs[j][lane];
            float v1 = Vs[j][lane + 32];
#pragma unroll
            for (int u = 0; u < 4; u++) {
                float pj = __shfl_sync(0xffffffffu, p[u], j);
                c0[u] += pj * v0;
                c1[u] += pj * v1;
            }
        }
        __syncthreads();
    }

#pragma unroll
    for (int u = 0; u < 4; u++) {
        float inv = 1.f / l[u];
        size_t ob = (size_t)(q0 + qrow + u) * Hdim + h * HDd;
        ctx[ob + lane]      = __float2half(c0[u] * inv);
        ctx[ob + lane + 32] = __float2half(c1[u] * inv);
    }
}

// ---------------------------------------------------------------------------
extern "C" void kernel_launch(void* const* d_in, const int* in_sizes, int n_in,
                              void* d_out, int out_size) {
    const float* x       = (const float*)d_in[0];
    const float* alibi   = (const float*)d_in[1];
    // d_in[2] = attention_mask (causal tril; computed arithmetically)
    const float* ln_w    = (const float*)d_in[3];
    const float* ln_b    = (const float*)d_in[4];
    const float* w_qkv   = (const float*)d_in[5];
    const float* w_dense = (const float*)d_in[6];
    const float* w_fc    = (const float*)d_in[7];
    const float* w_proj  = (const float*)d_in[8];
    float* out = (float*)d_out;

    float *p_qkv, *p_attn;
    __half *p_ln, *p_ctx, *p_fc, *pw_qkv, *pw_dense, *pw_fc, *pw_proj;
    cudaGetSymbolAddress((void**)&p_qkv,  g_qkv);
    cudaGetSymbolAddress((void**)&p_attn, g_attn);
    cudaGetSymbolAddress((void**)&p_ln,   g_ln_h);
    cudaGetSymbolAddress((void**)&p_ctx,  g_ctx_h);
    cudaGetSymbolAddress((void**)&p_fc,   g_fc_h);
    cudaGetSymbolAddress((void**)&pw_qkv,   g_w_qkv_h);
    cudaGetSymbolAddress((void**)&pw_dense, g_w_dense_h);
    cudaGetSymbolAddress((void**)&pw_fc,    g_w_fc_h);
    cudaGetSymbolAddress((void**)&pw_proj,  g_w_proj_h);

    cudaFuncSetAttribute(hgemm<0>, cudaFuncAttributeMaxDynamicSharedMemorySize, GEMM_SMEM);
    cudaFuncSetAttribute(hgemm<1>, cudaFuncAttributeMaxDynamicSharedMemorySize, GEMM_SMEM);
    cudaFuncSetAttribute(hgemm<2>, cudaFuncAttributeMaxDynamicSharedMemorySize, GEMM_SMEM);

    // Streams/events created once, before the first (uncaptured) run.
    static cudaStream_t s2 = nullptr, s3 = nullptr;
    static cudaEvent_t evQC = nullptr, evWFC = nullptr,
                       evFC = nullptr, evWD = nullptr, evWP = nullptr;
    if (s2 == nullptr) {
        cudaStreamCreateWithFlags(&s2, cudaStreamNonBlocking);
        cudaStreamCreateWithFlags(&s3, cudaStreamNonBlocking);
        cudaEventCreateWithFlags(&evQC,  cudaEventDisableTiming);
        cudaEventCreateWithFlags(&evWFC, cudaEventDisableTiming);
        cudaEventCreateWithFlags(&evFC,  cudaEventDisableTiming);
        cudaEventCreateWithFlags(&evWD,  cudaEventDisableTiming);
        cudaEventCreateWithFlags(&evWP,  cudaEventDisableTiming);
    }

    // main: LN first (needs only x), then the critical-path convert ALONE.
    ln_kernel<<<Sdim, 256>>>(x, ln_w, ln_b, p_ln);
    f2h_kernel<<<1184, 256>>>(w_qkv, pw_qkv, (size_t)Hdim * QKVN);
    cudaEventRecord(evQC, 0);

    // s2 (fork after qkv convert): fc convert overlaps the QKV GEMM,
    // then the fc GEMM shadows attention + dense.
    cudaStreamWaitEvent(s2, evQC, 0);
    f2h_kernel<<<1184, 256, 0, s2>>>(w_fc, pw_fc, (size_t)Hdim * FFNd);
    cudaEventRecord(evWFC, s2);
    hgemm<1><<<dim3(Sdim / BM, FFNd / BN), 256, GEMM_SMEM, s2>>>(
        p_ln, pw_fc, p_fc, FFNd, Hdim, nullptr, nullptr);
    cudaEventRecord(evFC, s2);

    // s3 (after fc convert): dense + proj weight converts, off critical path.
    cudaStreamWaitEvent(s3, evWFC, 0);
    f2h_kernel<<<1184, 256, 0, s3>>>(w_dense, pw_dense, (size_t)Hdim * Hdim);
    cudaEventRecord(evWD, s3);
    f2h_kernel<<<1184, 256, 0, s3>>>(w_proj, pw_proj, (size_t)FFNd * Hdim);
    cudaEventRecord(evWP, s3);

    // main: qkv chain
    hgemm<0><<<dim3(Sdim / BM, (QKVN + BN - 1) / BN), 256, GEMM_SMEM>>>(
        p_ln, pw_qkv, p_qkv, QKVN, Hdim, nullptr, nullptr);
    attn_kernel<<<dim3(NHh, Sdim / QB), 256>>>(p_qkv, alibi, p_ctx);

    // main: dense (needs ctx + w_dense)
    cudaStreamWaitEvent(0, evWD, 0);
    hgemm<0><<<dim3(Sdim / BM, (Hdim + BN - 1) / BN), 256, GEMM_SMEM>>>(
        p_ctx, pw_dense, p_attn, Hdim, Hdim, nullptr, nullptr);

    // main: proj (needs fc output + w_proj + dense output)
    cudaStreamWaitEvent(0, evFC, 0);
    cudaStreamWaitEvent(0, evWP, 0);
    hgemm<2><<<dim3(Sdim / BM, (Hdim + BN - 1) / BN), 256, GEMM_SMEM>>>(
        p_fc, pw_proj, out, Hdim, FFNd, x, p_attn);
}

// round 16
// speedup vs baseline: 1.0580x; 1.0580x over previous
#include <cuda_runtime.h>
#include <cuda_fp16.h>
#include <math.h>
#include <stdint.h>

#define Hdim 4544
#define Sdim 1024
#define NHh  71
#define HDd  64
#define FFNd 18176
#define QKVN 4672              // NH*HD + 2*HD
#define KOFF 4544
#define VOFF 4608
#define INV_NORM 0.125f
#define EPSf 1e-5f

// ---------------- scratch (__device__ globals; allocation-free rule) -------
__device__ __align__(16) float  g_qkv[Sdim * QKVN];
__device__ __align__(16) float  g_attn[Sdim * Hdim];
__device__ __align__(16) __half g_ln_h[Sdim * Hdim];
__device__ __align__(16) __half g_ctx_h[Sdim * Hdim];
__device__ __align__(16) __half g_fc_h[(size_t)Sdim * FFNd];
__device__ __align__(16) __half g_w_qkv_h[(size_t)Hdim * QKVN];
__device__ __align__(16) __half g_w_dense_h[(size_t)Hdim * Hdim];
__device__ __align__(16) __half g_w_fc_h[(size_t)Hdim * FFNd];
__device__ __align__(16) __half g_w_proj_h[(size_t)FFNd * Hdim];

// ---------------------------------------------------------------------------
// PTX helpers (compute_103-safe)
// ---------------------------------------------------------------------------
__device__ __forceinline__ uint32_t smem_u32(const void* p) {
    uint32_t a;
    asm("{ .reg .u64 t; cvta.to.shared.u64 t, %1; cvt.u32.u64 %0, t; }" : "=r"(a) : "l"(p));
    return a;
}

#define CP_ASYNC16(dst, src) \
    asm volatile("cp.async.cg.shared.global [%0], [%1], 16;" :: "r"(dst), "l"(src) : "memory")
#define CP_ASYNC16_Z(dst, src, sz) \
    asm volatile("cp.async.cg.shared.global [%0], [%1], 16, %2;" :: "r"(dst), "l"(src), "r"(sz) : "memory")
#define CP_COMMIT() asm volatile("cp.async.commit_group;" ::: "memory")
#define CP_WAIT1()  asm volatile("cp.async.wait_group 1;" ::: "memory")

#define LDSM_X4(r0, r1, r2, r3, addr)                                        \
    asm volatile("ldmatrix.sync.aligned.m8n8.x4.shared.b16 {%0,%1,%2,%3}, [%4];" \
        : "=r"(r0), "=r"(r1), "=r"(r2), "=r"(r3) : "r"(addr))
#define LDSM_X4T(r0, r1, r2, r3, addr)                                       \
    asm volatile("ldmatrix.sync.aligned.m8n8.x4.trans.shared.b16 {%0,%1,%2,%3}, [%4];" \
        : "=r"(r0), "=r"(r1), "=r"(r2), "=r"(r3) : "r"(addr))

__device__ __forceinline__ void mma_f16(float* c, const uint32_t* a,
                                        uint32_t b0, uint32_t b1) {
    asm volatile(
        "mma.sync.aligned.m16n8k16.row.col.f32.f16.f16.f32 "
        "{%0,%1,%2,%3}, {%4,%5,%6,%7}, {%8,%9}, {%0,%1,%2,%3};"
        : "+f"(c[0]), "+f"(c[1]), "+f"(c[2]), "+f"(c[3])
        : "r"(a[0]), "r"(a[1]), "r"(a[2]), "r"(a[3]), "r"(b0), "r"(b1));
}

// ---------------------------------------------------------------------------
// f16 mma GEMM:  C[1024, N] = A[1024, K](f16) @ B[K, N](f16)   row-major both
// CTA 128x128, BK=64, 8 warps (4m x 2n), warp tile 32x64, 3-stage cp.async.
// Smem layout: UNPADDED rows (A 128B, B 256B) with XOR swizzle
//   chunk16B ^= (row & 7)
// -> cp.async stores are line-contiguous (conflict-free) and all ldmatrix
//    phases hit distinct bank groups. 2 CTAs/SM.
// EPI: 0 none (fp32 out), 1 exact GELU (f16 out), 2 += r1 + r2 (fp32 out)
// ---------------------------------------------------------------------------
#define BM 128
#define BN 128
#define BK 64
#define A_SZ (BM * 128)        // 16384: 128 rows x 128B (64 f16)
#define B_SZ (BK * 256)        // 16384: 64 rows x 256B (128 f16)
#define STAGE_SZ (A_SZ + B_SZ) // 32768
#define NSTAGE 3
#define GEMM_SMEM (NSTAGE * STAGE_SZ)   // 98304

template <int EPI>
__global__ void __launch_bounds__(256, 2) hgemm(
    const __half* __restrict__ A, const __half* __restrict__ B,
    void* __restrict__ Cout, int N, int K,
    const float* __restrict__ r1, const float* __restrict__ r2) {
    extern __shared__ char smem[];
    uint32_t sb = smem_u32(smem);
    int tid = threadIdx.x;
    int m0 = blockIdx.x * BM, n0 = blockIdx.y * BN;
    int wid = tid >> 5, lane = tid & 31;
    int wm = (wid & 3) * 32, wn = (wid >> 2) * 64;
    int g = lane >> 2, q = lane & 3;

    float acc[2][8][4];
#pragma unroll
    for (int f = 0; f < 2; f++)
#pragma unroll
        for (int j = 0; j < 8; j++)
#pragma unroll
            for (int e = 0; e < 4; e++) acc[f][j][e] = 0.f;

    int nk = K / BK;

    auto issue = [&](int it) {
        uint32_t base = sb + (uint32_t)(it % NSTAGE) * STAGE_SZ;
        int k0 = it * BK;
        // A: 128 rows x 8 chunks, 4/thread, swizzled chunk placement
#pragma unroll
        for (int u = 0; u < 4; u++) {
            int ch = tid + u * 256;
            int r = ch >> 3, c = ch & 7;
            uint32_t dst = base + r * 128 + ((c ^ (r & 7)) << 4);
            CP_ASYNC16(dst, A + (size_t)(m0 + r) * K + k0 + c * 8);
        }
        // B: 64 rows x 16 chunks, 4/thread (zfill OOB n), swizzled
        uint32_t bb = base + A_SZ;
#pragma unroll
        for (int u = 0; u < 4; u++) {
            int ch = tid + u * 256;
            int r = ch >> 4, c = ch & 15;
            int col = n0 + c * 8;
            uint32_t sz = (col < N) ? 16u : 0u;
            const __half* src = B + (size_t)(k0 + r) * N + (col < N ? col : 0);
            uint32_t dst = bb + r * 256 + ((c ^ (r & 7)) << 4);
            CP_ASYNC16_Z(dst, src, sz);
        }
    };

    issue(0); CP_COMMIT();
    issue(1); CP_COMMIT();

    for (int i = 0; i < nk; i++) {
        CP_WAIT1();
        __syncthreads();
        if (i + 2 < nk) issue(i + 2);
        CP_COMMIT();

        uint32_t As = sb + (uint32_t)(i % NSTAGE) * STAGE_SZ;
        uint32_t Bs = As + A_SZ;
#pragma unroll
        for (int ks = 0; ks < 4; ks++) {
            uint32_t a[2][4];
#pragma unroll
            for (int f = 0; f < 2; f++) {
                int row = wm + f * 16 + (lane & 15);
                int chunk = 2 * ks + (lane >> 4);
                uint32_t addr = As + row * 128 + ((chunk ^ (row & 7)) << 4);
                LDSM_X4(a[f][0], a[f][1], a[f][2], a[f][3], addr);
            }
            uint32_t bf[8][2];
#pragma unroll
            for (int u = 0; u < 4; u++) {
                int row = ks * 16 + (lane & 15);
                int chunk = (wn >> 3) + 2 * u + (lane >> 4);
                uint32_t addr = Bs + row * 256 + ((chunk ^ (row & 7)) << 4);
                LDSM_X4T(bf[2 * u][0], bf[2 * u][1],
                         bf[2 * u + 1][0], bf[2 * u + 1][1], addr);
            }
#pragma unroll
            for (int f = 0; f < 2; f++)
#pragma unroll
                for (int j = 0; j < 8; j++)
                    mma_f16(acc[f][j], a[f], bf[j][0], bf[j][1]);
        }
    }

#pragma unroll
    for (int f = 0; f < 2; f++) {
        int row = m0 + wm + f * 16 + g;
#pragma unroll
        for (int j = 0; j < 8; j++) {
            int col = n0 + wn + 8 * j + 2 * q;
            if (col >= N) continue;
            float v[4] = {acc[f][j][0], acc[f][j][1], acc[f][j][2], acc[f][j][3]};
            if (EPI == 1) {
#pragma unroll
                for (int e = 0; e < 4; e++)
                    v[e] = 0.5f * v[e] * (1.0f + erff(v[e] * 0.70710678118654752f));
                __half* C = (__half*)Cout;
                *(__half2*)(C + (size_t)row * N + col) = __floats2half2_rn(v[0], v[1]);
                *(__half2*)(C + (size_t)(row + 8) * N + col) = __floats2half2_rn(v[2], v[3]);
            } else {
                float* C = (float*)Cout;
                if (EPI == 2) {
                    size_t i0 = (size_t)row * N + col;
                    size_t i1 = (size_t)(row + 8) * N + col;
                    float2 a0 = *(const float2*)(r1 + i0);
                    float2 b0v = *(const float2*)(r2 + i0);
                    float2 a1 = *(const float2*)(r1 + i1);
                    float2 b1v = *(const float2*)(r2 + i1);
                    v[0] += a0.x + b0v.x; v[1] += a0.y + b0v.y;
                    v[2] += a1.x + b1v.x; v[3] += a1.y + b1v.y;
                }
                *(float2*)(C + (size_t)row * N + col)       = make_float2(v[0], v[1]);
                *(float2*)(C + (size_t)(row + 8) * N + col) = make_float2(v[2], v[3]);
            }
        }
    }
}

// ---------------------------------------------------------------------------
// fp32 -> f16 convert
// ---------------------------------------------------------------------------
__global__ void f2h_kernel(const float* __restrict__ in, __half* __restrict__ out,
                           size_t n) {
    size_t i = ((size_t)blockIdx.x * blockDim.x + threadIdx.x) * 4;
    size_t stride = (size_t)gridDim.x * blockDim.x * 4;
    for (; i < n; i += stride) {
        float4 v = *(const float4*)(in + i);
        __half2 h0 = __floats2half2_rn(v.x, v.y);
        __half2 h1 = __floats2half2_rn(v.z, v.w);
        uint2 pk;
        pk.x = *(uint32_t*)&h0;
        pk.y = *(uint32_t*)&h1;
        *(uint2*)(out + i) = pk;
    }
}

// ---------------------------------------------------------------------------
// LayerNorm -> f16 out
// ---------------------------------------------------------------------------
__global__ void ln_kernel(const float* __restrict__ x,
                          const float* __restrict__ w,
                          const float* __restrict__ b,
                          __half* __restrict__ out) {
    int row = blockIdx.x;
    const float4* xr = (const float4*)(x + (size_t)row * Hdim);
    float s = 0.f, ss = 0.f;
    for (int i = threadIdx.x; i < Hdim / 4; i += blockDim.x) {
        float4 v = xr[i];
        s  += v.x + v.y + v.z + v.w;
        ss += v.x * v.x + v.y * v.y + v.z * v.z + v.w * v.w;
    }
    __shared__ float rs[256], rq[256];
    rs[threadIdx.x] = s; rq[threadIdx.x] = ss;
    __syncthreads();
    for (int st = 128; st > 0; st >>= 1) {
        if (threadIdx.x < st) {
            rs[threadIdx.x] += rs[threadIdx.x + st];
            rq[threadIdx.x] += rq[threadIdx.x + st];
        }
        __syncthreads();
    }
    float mean = rs[0] / (float)Hdim;
    float var  = rq[0] / (float)Hdim - mean * mean;
    float inv  = rsqrtf(var + EPSf);
    const float4* wr = (const float4*)w;
    const float4* br = (const float4*)b;
    __half* outr = out + (size_t)row * Hdim;
    for (int i = threadIdx.x; i < Hdim / 4; i += blockDim.x) {
        float4 v = xr[i], wv = wr[i], bv = br[i];
        float o0 = (v.x - mean) * inv * wv.x + bv.x;
        float o1 = (v.y - mean) * inv * wv.y + bv.y;
        float o2 = (v.z - mean) * inv * wv.z + bv.z;
        float o3 = (v.w - mean) * inv * wv.w + bv.w;
        __half2 h0 = __floats2half2_rn(o0, o1);
        __half2 h1 = __floats2half2_rn(o2, o3);
        uint2 pk;
        pk.x = *(uint32_t*)&h0;
        pk.y = *(uint32_t*)&h1;
        *(uint2*)(outr + i * 4) = pk;
    }
}

// ---------------------------------------------------------------------------
// Flash-style causal attention, 32 queries/block (4 per warp).
// Causal mask computed arithmetically.
// ---------------------------------------------------------------------------
#define QB 32
__global__ void __launch_bounds__(256) attn_kernel(
    const float* __restrict__ qkv,
    const float* __restrict__ alibi,
    __half* __restrict__ ctx) {
    __shared__ float Qs[QB][65];
    __shared__ float Ks[32][65];
    __shared__ float Vs[32][65];

    int h  = blockIdx.x;
    int q0 = blockIdx.y * QB;
    int t    = threadIdx.x;
    int w    = t >> 5;
    int lane = t & 31;
    int qrow = w * 4;

    for (int i = t; i < QB * 64; i += 256) {
        int r = i >> 6, d = i & 63;
        Qs[r][d] = qkv[(size_t)(q0 + r) * QKVN + h * HDd + d];
    }
    __syncthreads();

    float m[4], l[4], c0[4], c1[4], p[4];
#pragma unroll
    for (int u = 0; u < 4; u++) { m[u] = -INFINITY; l[u] = 0.f; c0[u] = 0.f; c1[u] = 0.f; }

    int kend = q0 + QB - 1;

    for (int kc = 0; kc <= kend; kc += 32) {
        for (int i = t; i < 2048; i += 256) {
            int j = i >> 6, d = i & 63;
            size_t rb = (size_t)(kc + j) * QKVN;
            Ks[j][d] = qkv[rb + KOFF + d];
            Vs[j][d] = qkv[rb + VOFF + d];
        }
        __syncthreads();

        int kg = kc + lane;
        float s[4] = {0.f, 0.f, 0.f, 0.f};
#pragma unroll
        for (int d = 0; d < 64; d++) {
            float kv = Ks[lane][d];
            s[0] += Qs[qrow + 0][d] * kv;
            s[1] += Qs[qrow + 1][d] * kv;
            s[2] += Qs[qrow + 2][d] * kv;
            s[3] += Qs[qrow + 3][d] * kv;
        }
        float al = alibi[h * Sdim + kg];
#pragma unroll
        for (int u = 0; u < 4; u++) {
            int qg = q0 + qrow + u;
            float msk = (kg <= qg) ? 0.0f : -1000000000.0f;
            float su = (s[u] + al) * INV_NORM + msk;
            float cm = su;
#pragma unroll
            for (int o = 16; o; o >>= 1)
                cm = fmaxf(cm, __shfl_xor_sync(0xffffffffu, cm, o));
            float mnew = fmaxf(m[u], cm);
            float corr = __expf(m[u] - mnew);
            p[u] = __expf(su - mnew);
            float ps = p[u];
#pragma unroll
            for (int o = 16; o; o >>= 1)
                ps += __shfl_xor_sync(0xffffffffu, ps, o);
            l[u] = l[u] * corr + ps;
            c0[u] *= corr; c1[u] *= corr;
            m[u] = mnew;
        }
#pragma unroll
        for (int j = 0; j < 32; j++) {
            float v0 = Vs[j][lane];
            float v1 = Vs[j][lane + 32];
#pragma unroll
            for (int u = 0; u < 4; u++) {
                float pj = __shfl_sync(0xffffffffu, p[u], j);
                c0[u] += pj * v0;
                c1[u] += pj * v1;
            }
        }
        __syncthreads();
    }

#pragma unroll
    for (int u = 0; u < 4; u++) {
        float inv = 1.f / l[u];
        size_t ob = (size_t)(q0 + qrow + u) * Hdim + h * HDd;
        ctx[ob + lane]      = __float2half(c0[u] * inv);
        ctx[ob + lane + 32] = __float2half(c1[u] * inv);
    }
}

// ---------------------------------------------------------------------------
extern "C" void kernel_launch(void* const* d_in, const int* in_sizes, int n_in,
                              void* d_out, int out_size) {
    const float* x       = (const float*)d_in[0];
    const float* alibi   = (const float*)d_in[1];
    // d_in[2] = attention_mask (causal tril; computed arithmetically)
    const float* ln_w    = (const float*)d_in[3];
    const float* ln_b    = (const float*)d_in[4];
    const float* w_qkv   = (const float*)d_in[5];
    const float* w_dense = (const float*)d_in[6];
    const float* w_fc    = (const float*)d_in[7];
    const float* w_proj  = (const float*)d_in[8];
    float* out = (float*)d_out;

    float *p_qkv, *p_attn;
    __half *p_ln, *p_ctx, *p_fc, *pw_qkv, *pw_dense, *pw_fc, *pw_proj;
    cudaGetSymbolAddress((void**)&p_qkv,  g_qkv);
    cudaGetSymbolAddress((void**)&p_attn, g_attn);
    cudaGetSymbolAddress((void**)&p_ln,   g_ln_h);
    cudaGetSymbolAddress((void**)&p_ctx,  g_ctx_h);
    cudaGetSymbolAddress((void**)&p_fc,   g_fc_h);
    cudaGetSymbolAddress((void**)&pw_qkv,   g_w_qkv_h);
    cudaGetSymbolAddress((void**)&pw_dense, g_w_dense_h);
    cudaGetSymbolAddress((void**)&pw_fc,    g_w_fc_h);
    cudaGetSymbolAddress((void**)&pw_proj,  g_w_proj_h);

    cudaFuncSetAttribute(hgemm<0>, cudaFuncAttributeMaxDynamicSharedMemorySize, GEMM_SMEM);
    cudaFuncSetAttribute(hgemm<1>, cudaFuncAttributeMaxDynamicSharedMemorySize, GEMM_SMEM);
    cudaFuncSetAttribute(hgemm<2>, cudaFuncAttributeMaxDynamicSharedMemorySize, GEMM_SMEM);

    // Streams/events created once, before the first (uncaptured) run.
    static cudaStream_t s2 = nullptr, s3 = nullptr;
    static cudaEvent_t evQC = nullptr, evWFC = nullptr,
                       evFC = nullptr, evWD = nullptr, evWP = nullptr;
    if (s2 == nullptr) {
        cudaStreamCreateWithFlags(&s2, cudaStreamNonBlocking);
        cudaStreamCreateWithFlags(&s3, cudaStreamNonBlocking);
        cudaEventCreateWithFlags(&evQC,  cudaEventDisableTiming);
        cudaEventCreateWithFlags(&evWFC, cudaEventDisableTiming);
        cudaEventCreateWithFlags(&evFC,  cudaEventDisableTiming);
        cudaEventCreateWithFlags(&evWD,  cudaEventDisableTiming);
        cudaEventCreateWithFlags(&evWP,  cudaEventDisableTiming);
    }

    // main: LN first (needs only x), then the critical-path convert ALONE.
    ln_kernel<<<Sdim, 256>>>(x, ln_w, ln_b, p_ln);
    f2h_kernel<<<1184, 256>>>(w_qkv, pw_qkv, (size_t)Hdim * QKVN);
    cudaEventRecord(evQC, 0);

    // s2 (fork after qkv convert): fc convert overlaps the QKV GEMM,
    // then the fc GEMM shadows attention + dense.
    cudaStreamWaitEvent(s2, evQC, 0);
    f2h_kernel<<<1184, 256, 0, s2>>>(w_fc, pw_fc, (size_t)Hdim * FFNd);
    cudaEventRecord(evWFC, s2);
    hgemm<1><<<dim3(Sdim / BM, FFNd / BN), 256, GEMM_SMEM, s2>>>(
        p_ln, pw_fc, p_fc, FFNd, Hdim, nullptr, nullptr);
    cudaEventRecord(evFC, s2);

    // s3 (after fc convert): dense + proj weight converts, off critical path.
    cudaStreamWaitEvent(s3, evWFC, 0);
    f2h_kernel<<<1184, 256, 0, s3>>>(w_dense, pw_dense, (size_t)Hdim * Hdim);
    cudaEventRecord(evWD, s3);
    f2h_kernel<<<1184, 256, 0, s3>>>(w_proj, pw_proj, (size_t)FFNd * Hdim);
    cudaEventRecord(evWP, s3);

    // main: qkv chain
    hgemm<0><<<dim3(Sdim / BM, (QKVN + BN - 1) / BN), 256, GEMM_SMEM>>>(
        p_ln, pw_qkv, p_qkv, QKVN, Hdim, nullptr, nullptr);
    attn_kernel<<<dim3(NHh, Sdim / QB), 256>>>(p_qkv, alibi, p_ctx);

    // main: dense (needs ctx + w_dense)
    cudaStreamWaitEvent(0, evWD, 0);
    hgemm<0><<<dim3(Sdim / BM, (Hdim + BN - 1) / BN), 256, GEMM_SMEM>>>(
        p_ctx, pw_dense, p_attn, Hdim, Hdim, nullptr, nullptr);

    // main: proj (needs fc output + w_proj + dense output)
    cudaStreamWaitEvent(0, evFC, 0);
    cudaStreamWaitEvent(0, evWP, 0);
    hgemm<2><<<dim3(Sdim / BM, (Hdim + BN - 1) / BN), 256, GEMM_SMEM>>>(
        p_fc, pw_proj, out, Hdim, FFNd, x, p_attn);
}

// round 17
// speedup vs baseline: 1.1281x; 1.0662x over previous
#include <cuda_runtime.h>
#include <cuda_fp16.h>
#include <math.h>
#include <stdint.h>

#define Hdim 4544
#define Sdim 1024
#define NHh  71
#define HDd  64
#define FFNd 18176
#define QKVN 4672              // NH*HD + 2*HD
#define KOFF 4544
#define VOFF 4608
#define INV_NORM 0.125f
#define EPSf 1e-5f

// ---------------- scratch (__device__ globals; allocation-free rule) -------
__device__ __align__(16) float  g_qkv[Sdim * QKVN];
__device__ __align__(16) float  g_attn[Sdim * Hdim];
__device__ __align__(16) __half g_ln_h[Sdim * Hdim];
__device__ __align__(16) __half g_ctx_h[Sdim * Hdim];
__device__ __align__(16) __half g_fc_h[(size_t)Sdim * FFNd];
__device__ __align__(16) __half g_w_qkv_h[(size_t)Hdim * QKVN];
__device__ __align__(16) __half g_w_dense_h[(size_t)Hdim * Hdim];
__device__ __align__(16) __half g_w_fc_h[(size_t)Hdim * FFNd];
__device__ __align__(16) __half g_w_proj_h[(size_t)FFNd * Hdim];

// ---------------------------------------------------------------------------
// PTX helpers (compute_103-safe)
// ---------------------------------------------------------------------------
__device__ __forceinline__ uint32_t smem_u32(const void* p) {
    uint32_t a;
    asm("{ .reg .u64 t; cvta.to.shared.u64 t, %1; cvt.u32.u64 %0, t; }" : "=r"(a) : "l"(p));
    return a;
}

#define CP_ASYNC16(dst, src) \
    asm volatile("cp.async.cg.shared.global [%0], [%1], 16;" :: "r"(dst), "l"(src) : "memory")
#define CP_ASYNC16_Z(dst, src, sz) \
    asm volatile("cp.async.cg.shared.global [%0], [%1], 16, %2;" :: "r"(dst), "l"(src), "r"(sz) : "memory")
#define CP_COMMIT() asm volatile("cp.async.commit_group;" ::: "memory")
#define CP_WAIT1()  asm volatile("cp.async.wait_group 1;" ::: "memory")

#define LDSM_X4(r0, r1, r2, r3, addr)                                        \
    asm volatile("ldmatrix.sync.aligned.m8n8.x4.shared.b16 {%0,%1,%2,%3}, [%4];" \
        : "=r"(r0), "=r"(r1), "=r"(r2), "=r"(r3) : "r"(addr))
#define LDSM_X4T(r0, r1, r2, r3, addr)                                       \
    asm volatile("ldmatrix.sync.aligned.m8n8.x4.trans.shared.b16 {%0,%1,%2,%3}, [%4];" \
        : "=r"(r0), "=r"(r1), "=r"(r2), "=r"(r3) : "r"(addr))

__device__ __forceinline__ void mma_f16(float* c, const uint32_t* a,
                                        uint32_t b0, uint32_t b1) {
    asm volatile(
        "mma.sync.aligned.m16n8k16.row.col.f32.f16.f16.f32 "
        "{%0,%1,%2,%3}, {%4,%5,%6,%7}, {%8,%9}, {%0,%1,%2,%3};"
        : "+f"(c[0]), "+f"(c[1]), "+f"(c[2]), "+f"(c[3])
        : "r"(a[0]), "r"(a[1]), "r"(a[2]), "r"(a[3]), "r"(b0), "r"(b1));
}

// ---------------------------------------------------------------------------
// f16 mma GEMM:  C[1024, N] = A[1024, K](f16) @ B[K, N](f16)   row-major both
// CTA 128x128, BK=64, 4 warps (2m x 2n), warp tile 64x64, 3-stage cp.async.
// XOR-swizzled unpadded smem (conflict-free). 2 CTAs/SM (8 warps).
// Warp tile 64x64 halves smem-read traffic per MMA vs 32x64: crossbar load
// (reads 1024cyc + stores 512cyc) now under the 2048cyc HMMA floor.
// EPI: 0 none (fp32 out), 1 exact GELU (f16 out), 2 += r1 + r2 (fp32 out)
// ---------------------------------------------------------------------------
#define BM 128
#define BN 128
#define BK 64
#define NTHR 128
#define A_SZ (BM * 128)        // 16384
#define B_SZ (BK * 256)        // 16384
#define STAGE_SZ (A_SZ + B_SZ) // 32768
#define NSTAGE 3
#define GEMM_SMEM (NSTAGE * STAGE_SZ)   // 98304

template <int EPI>
__global__ void __launch_bounds__(NTHR, 2) hgemm(
    const __half* __restrict__ A, const __half* __restrict__ B,
    void* __restrict__ Cout, int N, int K,
    const float* __restrict__ r1, const float* __restrict__ r2) {
    extern __shared__ char smem[];
    uint32_t sb = smem_u32(smem);
    int tid = threadIdx.x;
    int m0 = blockIdx.x * BM, n0 = blockIdx.y * BN;
    int wid = tid >> 5, lane = tid & 31;
    int wm = (wid & 1) * 64, wn = (wid >> 1) * 64;
    int g = lane >> 2, q = lane & 3;

    float acc[4][8][4];
#pragma unroll
    for (int f = 0; f < 4; f++)
#pragma unroll
        for (int j = 0; j < 8; j++)
#pragma unroll
            for (int e = 0; e < 4; e++) acc[f][j][e] = 0.f;

    int nk = K / BK;

    auto issue = [&](int it) {
        uint32_t base = sb + (uint32_t)(it % NSTAGE) * STAGE_SZ;
        int k0 = it * BK;
        // A: 128 rows x 8 chunks = 1024, 8/thread
#pragma unroll
        for (int u = 0; u < 8; u++) {
            int ch = tid + u * NTHR;
            int r = ch >> 3, c = ch & 7;
            uint32_t dst = base + r * 128 + ((c ^ (r & 7)) << 4);
            CP_ASYNC16(dst, A + (size_t)(m0 + r) * K + k0 + c * 8);
        }
        // B: 64 rows x 16 chunks = 1024, 8/thread (zfill OOB n)
        uint32_t bb = base + A_SZ;
#pragma unroll
        for (int u = 0; u < 8; u++) {
            int ch = tid + u * NTHR;
            int r = ch >> 4, c = ch & 15;
            int col = n0 + c * 8;
            uint32_t sz = (col < N) ? 16u : 0u;
            const __half* src = B + (size_t)(k0 + r) * N + (col < N ? col : 0);
            uint32_t dst = bb + r * 256 + ((c ^ (r & 7)) << 4);
            CP_ASYNC16_Z(dst, src, sz);
        }
    };

    issue(0); CP_COMMIT();
    issue(1); CP_COMMIT();

    for (int i = 0; i < nk; i++) {
        CP_WAIT1();
        __syncthreads();
        if (i + 2 < nk) issue(i + 2);
        CP_COMMIT();

        uint32_t As = sb + (uint32_t)(i % NSTAGE) * STAGE_SZ;
        uint32_t Bs = As + A_SZ;
#pragma unroll
        for (int ks = 0; ks < 4; ks++) {
            uint32_t a[4][4];
#pragma unroll
            for (int f = 0; f < 4; f++) {
                int row = wm + f * 16 + (lane & 15);
                int chunk = 2 * ks + (lane >> 4);
                uint32_t addr = As + row * 128 + ((chunk ^ (row & 7)) << 4);
                LDSM_X4(a[f][0], a[f][1], a[f][2], a[f][3], addr);
            }
            uint32_t bf[8][2];
#pragma unroll
            for (int u = 0; u < 4; u++) {
                int row = ks * 16 + (lane & 15);
                int chunk = (wn >> 3) + 2 * u + (lane >> 4);
                uint32_t addr = Bs + row * 256 + ((chunk ^ (row & 7)) << 4);
                LDSM_X4T(bf[2 * u][0], bf[2 * u][1],
                         bf[2 * u + 1][0], bf[2 * u + 1][1], addr);
            }
#pragma unroll
            for (int f = 0; f < 4; f++)
#pragma unroll
                for (int j = 0; j < 8; j++)
                    mma_f16(acc[f][j], a[f], bf[j][0], bf[j][1]);
        }
    }

#pragma unroll
    for (int f = 0; f < 4; f++) {
        int row = m0 + wm + f * 16 + g;
#pragma unroll
        for (int j = 0; j < 8; j++) {
            int col = n0 + wn + 8 * j + 2 * q;
            if (col >= N) continue;
            float v[4] = {acc[f][j][0], acc[f][j][1], acc[f][j][2], acc[f][j][3]};
            if (EPI == 1) {
#pragma unroll
                for (int e = 0; e < 4; e++)
                    v[e] = 0.5f * v[e] * (1.0f + erff(v[e] * 0.70710678118654752f));
                __half* C = (__half*)Cout;
                *(__half2*)(C + (size_t)row * N + col) = __floats2half2_rn(v[0], v[1]);
                *(__half2*)(C + (size_t)(row + 8) * N + col) = __floats2half2_rn(v[2], v[3]);
            } else {
                float* C = (float*)Cout;
                if (EPI == 2) {
                    size_t i0 = (size_t)row * N + col;
                    size_t i1 = (size_t)(row + 8) * N + col;
                    float2 a0 = *(const float2*)(r1 + i0);
                    float2 b0v = *(const float2*)(r2 + i0);
                    float2 a1 = *(const float2*)(r1 + i1);
                    float2 b1v = *(const float2*)(r2 + i1);
                    v[0] += a0.x + b0v.x; v[1] += a0.y + b0v.y;
                    v[2] += a1.x + b1v.x; v[3] += a1.y + b1v.y;
                }
                *(float2*)(C + (size_t)row * N + col)       = make_float2(v[0], v[1]);
                *(float2*)(C + (size_t)(row + 8) * N + col) = make_float2(v[2], v[3]);
            }
        }
    }
}

// ---------------------------------------------------------------------------
// fp32 -> f16 convert
// ---------------------------------------------------------------------------
__global__ void f2h_kernel(const float* __restrict__ in, __half* __restrict__ out,
                           size_t n) {
    size_t i = ((size_t)blockIdx.x * blockDim.x + threadIdx.x) * 4;
    size_t stride = (size_t)gridDim.x * blockDim.x * 4;
    for (; i < n; i += stride) {
        float4 v = *(const float4*)(in + i);
        __half2 h0 = __floats2half2_rn(v.x, v.y);
        __half2 h1 = __floats2half2_rn(v.z, v.w);
        uint2 pk;
        pk.x = *(uint32_t*)&h0;
        pk.y = *(uint32_t*)&h1;
        *(uint2*)(out + i) = pk;
    }
}

// ---------------------------------------------------------------------------
// LayerNorm -> f16 out
// ---------------------------------------------------------------------------
__global__ void ln_kernel(const float* __restrict__ x,
                          const float* __restrict__ w,
                          const float* __restrict__ b,
                          __half* __restrict__ out) {
    int row = blockIdx.x;
    const float4* xr = (const float4*)(x + (size_t)row * Hdim);
    float s = 0.f, ss = 0.f;
    for (int i = threadIdx.x; i < Hdim / 4; i += blockDim.x) {
        float4 v = xr[i];
        s  += v.x + v.y + v.z + v.w;
        ss += v.x * v.x + v.y * v.y + v.z * v.z + v.w * v.w;
    }
    __shared__ float rs[256], rq[256];
    rs[threadIdx.x] = s; rq[threadIdx.x] = ss;
    __syncthreads();
    for (int st = 128; st > 0; st >>= 1) {
        if (threadIdx.x < st) {
            rs[threadIdx.x] += rs[threadIdx.x + st];
            rq[threadIdx.x] += rq[threadIdx.x + st];
        }
        __syncthreads();
    }
    float mean = rs[0] / (float)Hdim;
    float var  = rq[0] / (float)Hdim - mean * mean;
    float inv  = rsqrtf(var + EPSf);
    const float4* wr = (const float4*)w;
    const float4* br = (const float4*)b;
    __half* outr = out + (size_t)row * Hdim;
    for (int i = threadIdx.x; i < Hdim / 4; i += blockDim.x) {
        float4 v = xr[i], wv = wr[i], bv = br[i];
        float o0 = (v.x - mean) * inv * wv.x + bv.x;
        float o1 = (v.y - mean) * inv * wv.y + bv.y;
        float o2 = (v.z - mean) * inv * wv.z + bv.z;
        float o3 = (v.w - mean) * inv * wv.w + bv.w;
        __half2 h0 = __floats2half2_rn(o0, o1);
        __half2 h1 = __floats2half2_rn(o2, o3);
        uint2 pk;
        pk.x = *(uint32_t*)&h0;
        pk.y = *(uint32_t*)&h1;
        *(uint2*)(outr + i * 4) = pk;
    }
}

// ---------------------------------------------------------------------------
// Flash-style causal attention, 32 queries/block (4 per warp).
// Causal mask computed arithmetically.
// ---------------------------------------------------------------------------
#define QB 32
__global__ void __launch_bounds__(256) attn_kernel(
    const float* __restrict__ qkv,
    const float* __restrict__ alibi,
    __half* __restrict__ ctx) {
    __shared__ float Qs[QB][65];
    __shared__ float Ks[32][65];
    __shared__ float Vs[32][65];

    int h  = blockIdx.x;
    int q0 = blockIdx.y * QB;
    int t    = threadIdx.x;
    int w    = t >> 5;
    int lane = t & 31;
    int qrow = w * 4;

    for (int i = t; i < QB * 64; i += 256) {
        int r = i >> 6, d = i & 63;
        Qs[r][d] = qkv[(size_t)(q0 + r) * QKVN + h * HDd + d];
    }
    __syncthreads();

    float m[4], l[4], c0[4], c1[4], p[4];
#pragma unroll
    for (int u = 0; u < 4; u++) { m[u] = -INFINITY; l[u] = 0.f; c0[u] = 0.f; c1[u] = 0.f; }

    int kend = q0 + QB - 1;

    for (int kc = 0; kc <= kend; kc += 32) {
        for (int i = t; i < 2048; i += 256) {
            int j = i >> 6, d = i & 63;
            size_t rb = (size_t)(kc + j) * QKVN;
            Ks[j][d] = qkv[rb + KOFF + d];
            Vs[j][d] = qkv[rb + VOFF + d];
        }
        __syncthreads();

        int kg = kc + lane;
        float s[4] = {0.f, 0.f, 0.f, 0.f};
#pragma unroll
        for (int d = 0; d < 64; d++) {
            float kv = Ks[lane][d];
            s[0] += Qs[qrow + 0][d] * kv;
            s[1] += Qs[qrow + 1][d] * kv;
            s[2] += Qs[qrow + 2][d] * kv;
            s[3] += Qs[qrow + 3][d] * kv;
        }
        float al = alibi[h * Sdim + kg];
#pragma unroll
        for (int u = 0; u < 4; u++) {
            int qg = q0 + qrow + u;
            float msk = (kg <= qg) ? 0.0f : -1000000000.0f;
            float su = (s[u] + al) * INV_NORM + msk;
            float cm = su;
#pragma unroll
            for (int o = 16; o; o >>= 1)
                cm = fmaxf(cm, __shfl_xor_sync(0xffffffffu, cm, o));
            float mnew = fmaxf(m[u], cm);
            float corr = __expf(m[u] - mnew);
            p[u] = __expf(su - mnew);
            float ps = p[u];
#pragma unroll
            for (int o = 16; o; o >>= 1)
                ps += __shfl_xor_sync(0xffffffffu, ps, o);
            l[u] = l[u] * corr + ps;
            c0[u] *= corr; c1[u] *= corr;
            m[u] = mnew;
        }
#pragma unroll
        for (int j = 0; j < 32; j++) {
            float v0 = Vs[j][lane];
            float v1 = Vs[j][lane + 32];
#pragma unroll
            for (int u = 0; u < 4; u++) {
                float pj = __shfl_sync(0xffffffffu, p[u], j);
                c0[u] += pj * v0;
                c1[u] += pj * v1;
            }
        }
        __syncthreads();
    }

#pragma unroll
    for (int u = 0; u < 4; u++) {
        float inv = 1.f / l[u];
        size_t ob = (size_t)(q0 + qrow + u) * Hdim + h * HDd;
        ctx[ob + lane]      = __float2half(c0[u] * inv);
        ctx[ob + lane + 32] = __float2half(c1[u] * inv);
    }
}

// ---------------------------------------------------------------------------
extern "C" void kernel_launch(void* const* d_in, const int* in_sizes, int n_in,
                              void* d_out, int out_size) {
    const float* x       = (const float*)d_in[0];
    const float* alibi   = (const float*)d_in[1];
    // d_in[2] = attention_mask (causal tril; computed arithmetically)
    const float* ln_w    = (const float*)d_in[3];
    const float* ln_b    = (const float*)d_in[4];
    const float* w_qkv   = (const float*)d_in[5];
    const float* w_dense = (const float*)d_in[6];
    const float* w_fc    = (const float*)d_in[7];
    const float* w_proj  = (const float*)d_in[8];
    float* out = (float*)d_out;

    float *p_qkv, *p_attn;
    __half *p_ln, *p_ctx, *p_fc, *pw_qkv, *pw_dense, *pw_fc, *pw_proj;
    cudaGetSymbolAddress((void**)&p_qkv,  g_qkv);
    cudaGetSymbolAddress((void**)&p_attn, g_attn);
    cudaGetSymbolAddress((void**)&p_ln,   g_ln_h);
    cudaGetSymbolAddress((void**)&p_ctx,  g_ctx_h);
    cudaGetSymbolAddress((void**)&p_fc,   g_fc_h);
    cudaGetSymbolAddress((void**)&pw_qkv,   g_w_qkv_h);
    cudaGetSymbolAddress((void**)&pw_dense, g_w_dense_h);
    cudaGetSymbolAddress((void**)&pw_fc,    g_w_fc_h);
    cudaGetSymbolAddress((void**)&pw_proj,  g_w_proj_h);

    cudaFuncSetAttribute(hgemm<0>, cudaFuncAttributeMaxDynamicSharedMemorySize, GEMM_SMEM);
    cudaFuncSetAttribute(hgemm<1>, cudaFuncAttributeMaxDynamicSharedMemorySize, GEMM_SMEM);
    cudaFuncSetAttribute(hgemm<2>, cudaFuncAttributeMaxDynamicSharedMemorySize, GEMM_SMEM);

    // Streams/events created once, before the first (uncaptured) run.
    static cudaStream_t s2 = nullptr, s3 = nullptr;
    static cudaEvent_t evQC = nullptr, evWFC = nullptr,
                       evFC = nullptr, evWD = nullptr, evWP = nullptr;
    if (s2 == nullptr) {
        cudaStreamCreateWithFlags(&s2, cudaStreamNonBlocking);
        cudaStreamCreateWithFlags(&s3, cudaStreamNonBlocking);
        cudaEventCreateWithFlags(&evQC,  cudaEventDisableTiming);
        cudaEventCreateWithFlags(&evWFC, cudaEventDisableTiming);
        cudaEventCreateWithFlags(&evFC,  cudaEventDisableTiming);
        cudaEventCreateWithFlags(&evWD,  cudaEventDisableTiming);
        cudaEventCreateWithFlags(&evWP,  cudaEventDisableTiming);
    }

    // main: LN first (needs only x), then the critical-path convert ALONE.
    ln_kernel<<<Sdim, 256>>>(x, ln_w, ln_b, p_ln);
    f2h_kernel<<<1184, 256>>>(w_qkv, pw_qkv, (size_t)Hdim * QKVN);
    cudaEventRecord(evQC, 0);

    // s2 (fork after qkv convert): fc convert overlaps the QKV GEMM,
    // then the fc GEMM shadows attention + dense.
    cudaStreamWaitEvent(s2, evQC, 0);
    f2h_kernel<<<1184, 256, 0, s2>>>(w_fc, pw_fc, (size_t)Hdim * FFNd);
    cudaEventRecord(evWFC, s2);
    hgemm<1><<<dim3(Sdim / BM, FFNd / BN), NTHR, GEMM_SMEM, s2>>>(
        p_ln, pw_fc, p_fc, FFNd, Hdim, nullptr, nullptr);
    cudaEventRecord(evFC, s2);

    // s3 (after fc convert): dense + proj weight converts, off critical path.
    cudaStreamWaitEvent(s3, evWFC, 0);
    f2h_kernel<<<1184, 256, 0, s3>>>(w_dense, pw_dense, (size_t)Hdim * Hdim);
    cudaEventRecord(evWD, s3);
    f2h_kernel<<<1184, 256, 0, s3>>>(w_proj, pw_proj, (size_t)FFNd * Hdim);
    cudaEventRecord(evWP, s3);

    // main: qkv chain
    hgemm<0><<<dim3(Sdim / BM, (QKVN + BN - 1) / BN), NTHR, GEMM_SMEM>>>(
        p_ln, pw_qkv, p_qkv, QKVN, Hdim, nullptr, nullptr);
    attn_kernel<<<dim3(NHh, Sdim / QB), 256>>>(p_qkv, alibi, p_ctx);

    // main: dense (needs ctx + w_dense)
    cudaStreamWaitEvent(0, evWD, 0);
    hgemm<0><<<dim3(Sdim / BM, (Hdim + BN - 1) / BN), NTHR, GEMM_SMEM>>>(
        p_ctx, pw_dense, p_attn, Hdim, Hdim, nullptr, nullptr);

    // main: proj (needs fc output + w_proj + dense output)
    cudaStreamWaitEvent(0, evFC, 0);
    cudaStreamWaitEvent(0, evWP, 0);
    hgemm<2><<<dim3(Sdim / BM, (Hdim + BN - 1) / BN), NTHR, GEMM_SMEM>>>(
        p_fc, pw_proj, out, Hdim, FFNd, x, p_attn);
}